// round 5
// baseline (speedup 1.0000x reference)
#include <cuda_runtime.h>
#include <stdint.h>

#define NEGF (-1e9f)

// ---------------- scratch (alloc-free: __device__ globals) ----------------
__device__ float g_S [16u * 1024u * 2048u];   // logits / probs  [B,NQ,NK]
__device__ float g_Vt[16u * 256u  * 2048u];   // V'^T = W @ V^T  [B,O,NK]

// ---------------- helpers ----------------
__device__ __forceinline__ uint32_t smem_u32(const void* p) {
    uint32_t a;
    asm("{ .reg .u64 t; cvta.to.shared.u64 t, %1; cvt.u32.u64 %0, t; }" : "=r"(a) : "l"(p));
    return a;
}
__device__ __forceinline__ uint32_t tf32u(uint32_t x) {
    uint32_t u;
    asm("cvt.rna.tf32.f32 %0, %1;" : "=r"(u) : "f"(__uint_as_float(x)));
    return u;
}
__device__ __forceinline__ float tf32r(float x) {
    uint32_t u;
    asm("cvt.rna.tf32.f32 %0, %1;" : "=r"(u) : "f"(x));
    return __uint_as_float(u);
}
__device__ __forceinline__ void mma_tf32(float c[4], const uint32_t a[4], const uint32_t b[2]) {
    asm volatile(
        "mma.sync.aligned.m16n8k8.row.col.f32.tf32.tf32.f32 "
        "{%0,%1,%2,%3}, {%4,%5,%6,%7}, {%8,%9}, {%0,%1,%2,%3};"
        : "+f"(c[0]), "+f"(c[1]), "+f"(c[2]), "+f"(c[3])
        : "r"(a[0]), "r"(a[1]), "r"(a[2]), "r"(a[3]), "r"(b[0]), "r"(b[1]));
}
__device__ __forceinline__ void ldsm4(uint32_t& r0, uint32_t& r1, uint32_t& r2, uint32_t& r3,
                                      uint32_t addr) {
    asm volatile("ldmatrix.sync.aligned.m8n8.x4.shared.b16 {%0,%1,%2,%3}, [%4];"
                 : "=r"(r0), "=r"(r1), "=r"(r2), "=r"(r3) : "r"(addr));
}
__device__ __forceinline__ void cpasync16(uint32_t dst, const void* src) {
    asm volatile("cp.async.cg.shared.global [%0], [%1], 16;" :: "r"(dst), "l"(src) : "memory");
}
#define CP_COMMIT() asm volatile("cp.async.commit_group;" ::: "memory")
#define CP_WAIT2()  asm volatile("cp.async.wait_group 2;" ::: "memory")

// ---------------- TF32 tensor-core GEMM (cp.async + ldmatrix + mma.sync) ----
// C[z][m][n] = sum_k A[z][m][k] * B[z][n][k]    (both K-major)
// EPI: 0 plain, 1 scale+mask(-1e9), 2 +bias[n]
// CTA tile 128x256x32, 8 warps as 2(M) x 4(N), warp tile 64x64. 4-stage ring.
constexpr int BM = 128, BN = 256, BK = 32, BKP = 36;   // padded stride (floats)
constexpr int NSTG = 4;
constexpr int STG_FLT  = (BM + BN) * BKP;              // 13824 floats / stage
constexpr int STG_B    = STG_FLT * 4;                  // 55296 bytes
constexpr int SMEM_DYN = NSTG * STG_B;                 // 221184 bytes

template <int EPI>
__global__ __launch_bounds__(256)
void gemm_tf32(const float* __restrict__ Ag, const float* __restrict__ Bg,
               float* __restrict__ Cg,
               int N, int K, long long sA, long long sB, long long sC,
               const int* __restrict__ maskg, long long sMask,
               const float* __restrict__ bias, float scale)
{
    extern __shared__ float smem[];

    const int tid  = threadIdx.x;
    const int lane = tid & 31;
    const int warp = tid >> 5;
    const int wm = (warp & 1) * 64;       // 2 warps along M
    const int wn = (warp >> 1) * 64;      // 4 warps along N, 64 cols each
    const int z  = blockIdx.z;
    const int m0 = blockIdx.y * BM;
    const int n0 = blockIdx.x * BN;

    const float* A = Ag + (size_t)z * sA;
    const float* B = Bg + (size_t)z * sB;

    const uint32_t sbase = smem_u32(smem);
    // ldmatrix per-thread byte offsets (smem row stride = BKP*4 = 144B)
    const uint32_t aRowB = (uint32_t)(wm + (lane & 15)) * (BKP * 4) + (uint32_t)(lane >> 4) * 16;
    const uint32_t bRowB = (uint32_t)(wn + (lane & 7) + ((lane >> 4) << 3)) * (BKP * 4)
                         + (uint32_t)((lane >> 3) & 1) * 16;

    const int KT = K / BK;

    // issue one chunk's cp.asyncs (12 x 16B per thread)
    auto issue_chunk = [&](int c) {
        const uint32_t stg = sbase + (uint32_t)(c & (NSTG - 1)) * STG_B;
        const int koff = c * BK;
#pragma unroll
        for (int i = 0; i < 4; i++) {
            int f = tid + 256 * i, r = f >> 3, q = (f & 7) * 4;
            cpasync16(stg + (uint32_t)(r * BKP + q) * 4,
                      A + (size_t)(m0 + r) * K + koff + q);
        }
#pragma unroll
        for (int i = 0; i < 8; i++) {
            int f = tid + 256 * i, r = f >> 3, q = (f & 7) * 4;
            cpasync16(stg + (uint32_t)((BM + r) * BKP + q) * 4,
                      B + (size_t)(n0 + r) * K + koff + q);
        }
    };

    float acc[4][8][4];
#pragma unroll
    for (int i = 0; i < 4; i++)
#pragma unroll
        for (int j = 0; j < 8; j++)
#pragma unroll
            for (int r = 0; r < 4; r++) acc[i][j][r] = 0.0f;

    // prologue: chunks 0..2 in flight (KT >= 3 for all our shapes)
    issue_chunk(0); CP_COMMIT();
    issue_chunk(1); CP_COMMIT();
    issue_chunk(2); CP_COMMIT();

    for (int kb = 0; kb < KT; ++kb) {
        CP_WAIT2();            // chunk kb landed
        __syncthreads();       // all warps done with stage (kb+3)%4's previous life
        if (kb + 3 < KT) issue_chunk(kb + 3);
        CP_COMMIT();

        const uint32_t curBase = sbase + (uint32_t)(kb & (NSTG - 1)) * STG_B;
        const uint32_t aB = curBase + aRowB;
        const uint32_t bB = curBase + (uint32_t)(BM * BKP * 4) + bRowB;

        uint32_t af[2][4][4], bf[2][8][2];

        auto ldfr = [&](int buf, int ks) {
            const uint32_t kB = (uint32_t)ks * 32;
#pragma unroll
            for (int mi = 0; mi < 4; mi++)
                ldsm4(af[buf][mi][0], af[buf][mi][1], af[buf][mi][2], af[buf][mi][3],
                      aB + (uint32_t)mi * (16 * BKP * 4) + kB);
#pragma unroll
            for (int pr = 0; pr < 4; pr++)
                ldsm4(bf[buf][2 * pr][0], bf[buf][2 * pr][1],
                      bf[buf][2 * pr + 1][0], bf[buf][2 * pr + 1][1],
                      bB + (uint32_t)pr * (16 * BKP * 4) + kB);
        };
        auto cvtfr = [&](int buf) {
#pragma unroll
            for (int mi = 0; mi < 4; mi++)
#pragma unroll
                for (int r = 0; r < 4; r++) af[buf][mi][r] = tf32u(af[buf][mi][r]);
#pragma unroll
            for (int ni = 0; ni < 8; ni++) {
                bf[buf][ni][0] = tf32u(bf[buf][ni][0]);
                bf[buf][ni][1] = tf32u(bf[buf][ni][1]);
            }
        };

        ldfr(0, 0);
#pragma unroll
        for (int ks = 0; ks < 4; ++ks) {
            const int cur = ks & 1;
            if (ks < 3) ldfr(cur ^ 1, ks + 1);    // prefetch next fragments
            cvtfr(cur);
#pragma unroll
            for (int mi = 0; mi < 4; mi++)
#pragma unroll
                for (int ni = 0; ni < 8; ni++)
                    mma_tf32(acc[mi][ni], af[cur][mi], bf[cur][ni]);
        }
    }

    // ---------------- epilogue ----------------
    float* C = Cg + (size_t)z * sC;
    const int* Mk = (EPI == 1) ? (maskg + (size_t)z * sMask) : (const int*)0;

#pragma unroll
    for (int mi = 0; mi < 4; mi++) {
#pragma unroll
        for (int ni = 0; ni < 8; ni++) {
            const int row0 = m0 + wm + mi * 16 + (lane >> 2);
            const int col  = n0 + wn + ni * 8 + (lane & 3) * 2;
#pragma unroll
            for (int h = 0; h < 2; ++h) {
                const int row = row0 + h * 8;
                float v0 = acc[mi][ni][2 * h];
                float v1 = acc[mi][ni][2 * h + 1];
                if (EPI == 1) {
                    v0 *= scale; v1 *= scale;
                    int2 mk = *(const int2*)(Mk + (size_t)row * N + col);
                    if (mk.x == 0) v0 = NEGF;
                    if (mk.y == 0) v1 = NEGF;
                } else if (EPI == 2) {
                    v0 += bias[col];
                    v1 += bias[col + 1];
                }
                float2 o; o.x = v0; o.y = v1;
                *(float2*)(C + (size_t)row * N + col) = o;
            }
        }
    }
}

// ---------------- row softmax over NK=2048 ----------------
__global__ __launch_bounds__(256)
void softmax_rows(float* __restrict__ S)
{
    float* row = S + (size_t)blockIdx.x * 2048;
    const int tid = threadIdx.x;

    float4 a = reinterpret_cast<float4*>(row)[tid];
    float4 b = reinterpret_cast<float4*>(row)[tid + 256];

    float m = fmaxf(fmaxf(fmaxf(a.x, a.y), fmaxf(a.z, a.w)),
                    fmaxf(fmaxf(b.x, b.y), fmaxf(b.z, b.w)));
#pragma unroll
    for (int o = 16; o; o >>= 1) m = fmaxf(m, __shfl_xor_sync(0xffffffffu, m, o));

    __shared__ float red[8];
    if ((tid & 31) == 0) red[tid >> 5] = m;
    __syncthreads();
    m = red[0];
#pragma unroll
    for (int i = 1; i < 8; i++) m = fmaxf(m, red[i]);

    a.x = __expf(a.x - m); a.y = __expf(a.y - m); a.z = __expf(a.z - m); a.w = __expf(a.w - m);
    b.x = __expf(b.x - m); b.y = __expf(b.y - m); b.z = __expf(b.z - m); b.w = __expf(b.w - m);

    float s = (a.x + a.y) + (a.z + a.w) + (b.x + b.y) + (b.z + b.w);
#pragma unroll
    for (int o = 16; o; o >>= 1) s += __shfl_xor_sync(0xffffffffu, s, o);

    __syncthreads();
    if ((tid & 31) == 0) red[tid >> 5] = s;
    __syncthreads();
    s = red[0];
#pragma unroll
    for (int i = 1; i < 8; i++) s += red[i];

    const float inv = 1.0f / s;
    a.x *= inv; a.y *= inv; a.z *= inv; a.w *= inv;
    b.x *= inv; b.y *= inv; b.z *= inv; b.w *= inv;

    reinterpret_cast<float4*>(row)[tid]       = a;
    reinterpret_cast<float4*>(row)[tid + 256] = b;
}

// ---------------- launch ----------------
extern "C" void kernel_launch(void* const* d_in, const int* in_sizes, int n_in,
                              void* d_out, int out_size)
{
    const float* keys    = (const float*)d_in[0];   // [16, 2048, 512]
    const float* queries = (const float*)d_in[1];   // [16, 1024, 512]
    const float* values  = (const float*)d_in[2];   // [16, 2048, 512]
    const int*   mask    = (const int*)  d_in[3];   // [16, 1024, 2048]
    const float* W       = (const float*)d_in[4];   // [256, 512]
    const float* bias    = (const float*)d_in[5];   // [256]
    float* out = (float*)d_out;                     // [16, 1024, 256]

    const int B = 16, NQ = 1024, NK = 2048, D = 512, V = 512, O = 256;
    const float scale = 1.0f / sqrtf(512.0f);       // KQ = 512

    float* S = nullptr;  float* Vt = nullptr;
    cudaGetSymbolAddress((void**)&S,  g_S);
    cudaGetSymbolAddress((void**)&Vt, g_Vt);

    cudaFuncSetAttribute(gemm_tf32<0>, cudaFuncAttributeMaxDynamicSharedMemorySize, SMEM_DYN);
    cudaFuncSetAttribute(gemm_tf32<1>, cudaFuncAttributeMaxDynamicSharedMemorySize, SMEM_DYN);
    cudaFuncSetAttribute(gemm_tf32<2>, cudaFuncAttributeMaxDynamicSharedMemorySize, SMEM_DYN);

    // K0: Vt[b][o][n] = sum_v W[o][v] * values[b][n][v]
    gemm_tf32<0><<<dim3(NK / BN, O / BM, B), 256, SMEM_DYN>>>(
        W, values, Vt, NK, V,
        0LL, (long long)NK * V, (long long)O * NK,
        nullptr, 0LL, nullptr, 0.0f);

    // K1: S[b][q][k] = scale * <Q,K>, mask==0 -> -1e9
    gemm_tf32<1><<<dim3(NK / BN, NQ / BM, B), 256, SMEM_DYN>>>(
        queries, keys, S, NK, D,
        (long long)NQ * D, (long long)NK * D, (long long)NQ * NK,
        mask, (long long)NQ * NK, nullptr, scale);

    // K2: softmax over last dim
    softmax_rows<<<B * NQ, 256>>>(S);

    // K3: out[b][q][o] = sum_k P[b][q][k] * Vt[b][o][k] + bias[o]
    gemm_tf32<2><<<dim3(O / BN, NQ / BM, B), 256, SMEM_DYN>>>(
        S, Vt, out, O, NK,
        (long long)NQ * NK, (long long)O * NK, (long long)NQ * O,
        nullptr, 0LL, bias, 1.0f);
}

// round 6
// speedup vs baseline: 1.6158x; 1.6158x over previous
#include <cuda_runtime.h>
#include <cuda_fp16.h>
#include <stdint.h>

// ---------------- scratch (alloc-free: __device__ globals) ----------------
__device__ __half g_S [16u * 1024u * 2048u];   // logits / probs  [B,NQ,NK]  fp16
__device__ __half g_Vt[16u * 256u  * 2048u];   // V'^T = W @ V^T  [B,O,NK]   fp16

#define MASKV (-60000.0f)   // fp16-representable "minus infinity"; exp(x - max) -> 0,
                            // and all-masked rows still produce a uniform softmax.

// ---------------- helpers ----------------
__device__ __forceinline__ uint32_t smem_u32(const void* p) {
    uint32_t a;
    asm("{ .reg .u64 t; cvta.to.shared.u64 t, %1; cvt.u32.u64 %0, t; }" : "=r"(a) : "l"(p));
    return a;
}
__device__ __forceinline__ uint32_t f16x2(float lo, float hi) {
    uint32_t u;
    asm("cvt.rn.f16x2.f32 %0, %1, %2;" : "=r"(u) : "f"(hi), "f"(lo));
    return u;
}
__device__ __forceinline__ void mma_f16(float c[4], const uint32_t a[4], const uint32_t b[2]) {
    asm volatile(
        "mma.sync.aligned.m16n8k16.row.col.f32.f16.f16.f32 "
        "{%0,%1,%2,%3}, {%4,%5,%6,%7}, {%8,%9}, {%0,%1,%2,%3};"
        : "+f"(c[0]), "+f"(c[1]), "+f"(c[2]), "+f"(c[3])
        : "r"(a[0]), "r"(a[1]), "r"(a[2]), "r"(a[3]), "r"(b[0]), "r"(b[1]));
}
__device__ __forceinline__ void ldsm4(uint32_t& r0, uint32_t& r1, uint32_t& r2, uint32_t& r3,
                                      uint32_t addr) {
    asm volatile("ldmatrix.sync.aligned.m8n8.x4.shared.b16 {%0,%1,%2,%3}, [%4];"
                 : "=r"(r0), "=r"(r1), "=r"(r2), "=r"(r3) : "r"(addr));
}
__device__ __forceinline__ void sts64(uint32_t a, uint32_t x, uint32_t y) {
    asm volatile("st.shared.v2.b32 [%0], {%1,%2};" :: "r"(a), "r"(x), "r"(y) : "memory");
}
__device__ __forceinline__ void sts128(uint32_t a, uint4 v) {
    asm volatile("st.shared.v4.b32 [%0], {%1,%2,%3,%4};"
                 :: "r"(a), "r"(v.x), "r"(v.y), "r"(v.z), "r"(v.w) : "memory");
}

// ---------------- tiling ----------------
// CTA tile 128x256x32, 8 warps as 2(M) x 4(N), warp tile 64x64.
// fp16 smem rows: 32 halfs = 64B data, stride 80B => ldmatrix 8-row groups hit
// start-banks {0,20,8,28,16,4,24,12}: all 32 banks exactly once. Conflict-free.
constexpr int BM = 128, BN = 256, BK = 32;
constexpr int SBH   = 80;                 // bytes per smem row
constexpr int A_B   = BM * SBH;           // 10240
constexpr int STG_B = (BM + BN) * SBH;    // 30720 per stage
constexpr int SMEM_DYN = 2 * STG_B;       // 61440

// ===================== GEMM: fp32 inputs -> fp16 output =====================
// C[z][m][n] = sum_k A[z][m][k] * B[z][n][k]
// EPI 0: plain (K0: Vt).  EPI 1: scale + mask -> MASKV (K1: logits)
template <int EPI>
__global__ __launch_bounds__(256)
void gemm_a32(const float* __restrict__ Ag, const float* __restrict__ Bg,
              __half* __restrict__ Cg, int N, int K,
              long long sA, long long sB, long long sC,
              const int* __restrict__ maskg, long long sMask, float scale)
{
    extern __shared__ char smem[];

    const int tid  = threadIdx.x;
    const int lane = tid & 31;
    const int warp = tid >> 5;
    const int wm = (warp & 1) * 64;
    const int wn = (warp >> 1) * 64;
    const int z  = blockIdx.z;
    const int m0 = blockIdx.y * BM;
    const int n0 = blockIdx.x * BN;

    const float* A = Ag + (size_t)z * sA;
    const float* B = Bg + (size_t)z * sB;

    const uint32_t sbase = smem_u32(smem);
    const uint32_t aRowB = (uint32_t)(wm + (lane & 15)) * SBH + (uint32_t)(lane >> 4) * 16;
    const uint32_t bRowB = (uint32_t)(wn + (lane & 7) + ((lane >> 4) << 3)) * SBH
                         + (uint32_t)((lane >> 3) & 1) * 16;
    const int KT = K / BK;

    float4 ra[4], rb[8];
    auto load_regs = [&](int c) {
        const int koff = c * BK;
#pragma unroll
        for (int i = 0; i < 4; i++) {
            int f = tid + 256 * i, r = f >> 3, q = (f & 7) * 4;
            ra[i] = *(const float4*)(A + (size_t)(m0 + r) * K + koff + q);
        }
#pragma unroll
        for (int i = 0; i < 8; i++) {
            int f = tid + 256 * i, r = f >> 3, q = (f & 7) * 4;
            rb[i] = *(const float4*)(B + (size_t)(n0 + r) * K + koff + q);
        }
    };
    auto store_stage = [&](int s) {
        const uint32_t st = sbase + (uint32_t)s * STG_B;
#pragma unroll
        for (int i = 0; i < 4; i++) {
            int f = tid + 256 * i, r = f >> 3, q = (f & 7) * 4;
            sts64(st + (uint32_t)r * SBH + (uint32_t)q * 2,
                  f16x2(ra[i].x, ra[i].y), f16x2(ra[i].z, ra[i].w));
        }
#pragma unroll
        for (int i = 0; i < 8; i++) {
            int f = tid + 256 * i, r = f >> 3, q = (f & 7) * 4;
            sts64(st + (uint32_t)A_B + (uint32_t)r * SBH + (uint32_t)q * 2,
                  f16x2(rb[i].x, rb[i].y), f16x2(rb[i].z, rb[i].w));
        }
    };

    float acc[4][8][4];
#pragma unroll
    for (int i = 0; i < 4; i++)
#pragma unroll
        for (int j = 0; j < 8; j++)
#pragma unroll
            for (int r = 0; r < 4; r++) acc[i][j][r] = 0.0f;

    load_regs(0);
    store_stage(0);
    __syncthreads();
    if (KT > 1) load_regs(1);

    for (int kb = 0; kb < KT; ++kb) {
        const int cur = kb & 1;
        if (kb + 1 < KT) store_stage(cur ^ 1);
        if (kb + 2 < KT) load_regs(kb + 2);

        const uint32_t curBase = sbase + (uint32_t)cur * STG_B;
        const uint32_t aB = curBase + aRowB;
        const uint32_t bB = curBase + (uint32_t)A_B + bRowB;

#pragma unroll
        for (int ks = 0; ks < 2; ++ks) {                // 2 x K=16 per chunk
            const uint32_t kB = (uint32_t)ks * 32;
            uint32_t af[4][4], bf[8][2];
#pragma unroll
            for (int mi = 0; mi < 4; mi++)
                ldsm4(af[mi][0], af[mi][1], af[mi][2], af[mi][3],
                      aB + (uint32_t)mi * (16 * SBH) + kB);
#pragma unroll
            for (int pr = 0; pr < 4; pr++)
                ldsm4(bf[2 * pr][0], bf[2 * pr][1], bf[2 * pr + 1][0], bf[2 * pr + 1][1],
                      bB + (uint32_t)pr * (16 * SBH) + kB);
#pragma unroll
            for (int mi = 0; mi < 4; mi++)
#pragma unroll
                for (int ni = 0; ni < 8; ni++)
                    mma_f16(acc[mi][ni], af[mi], bf[ni]);
        }
        __syncthreads();
    }

    // ---------------- epilogue: fp16 out ----------------
    __half* C = Cg + (size_t)z * sC;
    const int* Mk = (EPI == 1) ? (maskg + (size_t)z * sMask) : (const int*)0;

#pragma unroll
    for (int mi = 0; mi < 4; mi++) {
#pragma unroll
        for (int ni = 0; ni < 8; ni++) {
            const int row0 = m0 + wm + mi * 16 + (lane >> 2);
            const int col  = n0 + wn + ni * 8 + (lane & 3) * 2;
#pragma unroll
            for (int h = 0; h < 2; ++h) {
                const int row = row0 + h * 8;
                float v0 = acc[mi][ni][2 * h];
                float v1 = acc[mi][ni][2 * h + 1];
                if (EPI == 1) {
                    v0 *= scale; v1 *= scale;
                    int2 mk = *(const int2*)(Mk + (size_t)row * N + col);
                    if (mk.x == 0) v0 = MASKV;
                    if (mk.y == 0) v1 = MASKV;
                }
                *(__half2*)(C + (size_t)row * N + col) = __floats2half2_rn(v0, v1);
            }
        }
    }
}

// ===================== GEMM: fp16 inputs -> fp32 output + bias (K3) ========
__global__ __launch_bounds__(256)
void gemm_h16(const __half* __restrict__ Ag, const __half* __restrict__ Bg,
              float* __restrict__ Cg, int N, int K,
              long long sA, long long sB, long long sC,
              const float* __restrict__ bias)
{
    extern __shared__ char smem[];

    const int tid  = threadIdx.x;
    const int lane = tid & 31;
    const int warp = tid >> 5;
    const int wm = (warp & 1) * 64;
    const int wn = (warp >> 1) * 64;
    const int z  = blockIdx.z;
    const int m0 = blockIdx.y * BM;
    const int n0 = blockIdx.x * BN;

    const __half* A = Ag + (size_t)z * sA;
    const __half* B = Bg + (size_t)z * sB;

    const uint32_t sbase = smem_u32(smem);
    const uint32_t aRowB = (uint32_t)(wm + (lane & 15)) * SBH + (uint32_t)(lane >> 4) * 16;
    const uint32_t bRowB = (uint32_t)(wn + (lane & 7) + ((lane >> 4) << 3)) * SBH
                         + (uint32_t)((lane >> 3) & 1) * 16;
    const int KT = K / BK;

    uint4 ra[2], rb[4];
    auto load_regs = [&](int c) {
        const int koff = c * BK;
#pragma unroll
        for (int i = 0; i < 2; i++) {                   // A: 128 rows x 4 segs
            int f = tid + 256 * i, r = f >> 2, sg = f & 3;
            ra[i] = *(const uint4*)(A + (size_t)(m0 + r) * K + koff + sg * 8);
        }
#pragma unroll
        for (int i = 0; i < 4; i++) {                   // B: 256 rows x 4 segs
            int f = tid + 256 * i, r = f >> 2, sg = f & 3;
            rb[i] = *(const uint4*)(B + (size_t)(n0 + r) * K + koff + sg * 8);
        }
    };
    auto store_stage = [&](int s) {
        const uint32_t st = sbase + (uint32_t)s * STG_B;
#pragma unroll
        for (int i = 0; i < 2; i++) {
            int f = tid + 256 * i, r = f >> 2, sg = f & 3;
            sts128(st + (uint32_t)r * SBH + (uint32_t)sg * 16, ra[i]);
        }
#pragma unroll
        for (int i = 0; i < 4; i++) {
            int f = tid + 256 * i, r = f >> 2, sg = f & 3;
            sts128(st + (uint32_t)A_B + (uint32_t)r * SBH + (uint32_t)sg * 16, rb[i]);
        }
    };

    float acc[4][8][4];
#pragma unroll
    for (int i = 0; i < 4; i++)
#pragma unroll
        for (int j = 0; j < 8; j++)
#pragma unroll
            for (int r = 0; r < 4; r++) acc[i][j][r] = 0.0f;

    load_regs(0);
    store_stage(0);
    __syncthreads();
    if (KT > 1) load_regs(1);

    for (int kb = 0; kb < KT; ++kb) {
        const int cur = kb & 1;
        if (kb + 1 < KT) store_stage(cur ^ 1);
        if (kb + 2 < KT) load_regs(kb + 2);

        const uint32_t curBase = sbase + (uint32_t)cur * STG_B;
        const uint32_t aB = curBase + aRowB;
        const uint32_t bB = curBase + (uint32_t)A_B + bRowB;

#pragma unroll
        for (int ks = 0; ks < 2; ++ks) {
            const uint32_t kB = (uint32_t)ks * 32;
            uint32_t af[4][4], bf[8][2];
#pragma unroll
            for (int mi = 0; mi < 4; mi++)
                ldsm4(af[mi][0], af[mi][1], af[mi][2], af[mi][3],
                      aB + (uint32_t)mi * (16 * SBH) + kB);
#pragma unroll
            for (int pr = 0; pr < 4; pr++)
                ldsm4(bf[2 * pr][0], bf[2 * pr][1], bf[2 * pr + 1][0], bf[2 * pr + 1][1],
                      bB + (uint32_t)pr * (16 * SBH) + kB);
#pragma unroll
            for (int mi = 0; mi < 4; mi++)
#pragma unroll
                for (int ni = 0; ni < 8; ni++)
                    mma_f16(acc[mi][ni], af[mi], bf[ni]);
        }
        __syncthreads();
    }

    // ---------------- epilogue: fp32 out + bias ----------------
    float* C = Cg + (size_t)z * sC;
#pragma unroll
    for (int mi = 0; mi < 4; mi++) {
#pragma unroll
        for (int ni = 0; ni < 8; ni++) {
            const int row0 = m0 + wm + mi * 16 + (lane >> 2);
            const int col  = n0 + wn + ni * 8 + (lane & 3) * 2;
            const float b0 = bias[col], b1 = bias[col + 1];
#pragma unroll
            for (int h = 0; h < 2; ++h) {
                const int row = row0 + h * 8;
                float2 o;
                o.x = acc[mi][ni][2 * h]     + b0;
                o.y = acc[mi][ni][2 * h + 1] + b1;
                *(float2*)(C + (size_t)row * N + col) = o;
            }
        }
    }
}

// ---------------- row softmax over NK=2048, fp16 in/out ----------------
__global__ __launch_bounds__(256)
void softmax_rows_h(__half* __restrict__ S)
{
    __half* row = S + (size_t)blockIdx.x * 2048;
    const int tid = threadIdx.x;

    float4 raw = reinterpret_cast<float4*>(row)[tid];   // 8 halfs
    __half2* hp = (__half2*)&raw;
    float2 f[4];
#pragma unroll
    for (int i = 0; i < 4; i++) f[i] = __half22float2(hp[i]);

    float m = fmaxf(fmaxf(fmaxf(f[0].x, f[0].y), fmaxf(f[1].x, f[1].y)),
                    fmaxf(fmaxf(f[2].x, f[2].y), fmaxf(f[3].x, f[3].y)));
#pragma unroll
    for (int o = 16; o; o >>= 1) m = fmaxf(m, __shfl_xor_sync(0xffffffffu, m, o));

    __shared__ float red[8];
    if ((tid & 31) == 0) red[tid >> 5] = m;
    __syncthreads();
    m = red[0];
#pragma unroll
    for (int i = 1; i < 8; i++) m = fmaxf(m, red[i]);

    float s = 0.0f;
#pragma unroll
    for (int i = 0; i < 4; i++) {
        f[i].x = __expf(f[i].x - m);
        f[i].y = __expf(f[i].y - m);
        s += f[i].x + f[i].y;
    }
#pragma unroll
    for (int o = 16; o; o >>= 1) s += __shfl_xor_sync(0xffffffffu, s, o);

    __syncthreads();
    if ((tid & 31) == 0) red[tid >> 5] = s;
    __syncthreads();
    s = red[0];
#pragma unroll
    for (int i = 1; i < 8; i++) s += red[i];

    const float inv = 1.0f / s;
#pragma unroll
    for (int i = 0; i < 4; i++)
        hp[i] = __floats2half2_rn(f[i].x * inv, f[i].y * inv);
    reinterpret_cast<float4*>(row)[tid] = raw;
}

// ---------------- launch ----------------
extern "C" void kernel_launch(void* const* d_in, const int* in_sizes, int n_in,
                              void* d_out, int out_size)
{
    const float* keys    = (const float*)d_in[0];   // [16, 2048, 512]
    const float* queries = (const float*)d_in[1];   // [16, 1024, 512]
    const float* values  = (const float*)d_in[2];   // [16, 2048, 512]
    const int*   mask    = (const int*)  d_in[3];   // [16, 1024, 2048]
    const float* W       = (const float*)d_in[4];   // [256, 512]
    const float* bias    = (const float*)d_in[5];   // [256]
    float* out = (float*)d_out;                     // [16, 1024, 256]

    const int B = 16, NQ = 1024, NK = 2048, D = 512, V = 512, O = 256;
    const float scale = 1.0f / sqrtf(512.0f);       // KQ = 512

    __half* S = nullptr;  __half* Vt = nullptr;
    cudaGetSymbolAddress((void**)&S,  g_S);
    cudaGetSymbolAddress((void**)&Vt, g_Vt);

    cudaFuncSetAttribute(gemm_a32<0>, cudaFuncAttributeMaxDynamicSharedMemorySize, SMEM_DYN);
    cudaFuncSetAttribute(gemm_a32<1>, cudaFuncAttributeMaxDynamicSharedMemorySize, SMEM_DYN);
    cudaFuncSetAttribute(gemm_h16,    cudaFuncAttributeMaxDynamicSharedMemorySize, SMEM_DYN);

    // K0: Vt[b][o][n] = sum_v W[o][v] * values[b][n][v]     -> fp16
    gemm_a32<0><<<dim3(NK / BN, O / BM, B), 256, SMEM_DYN>>>(
        W, values, Vt, NK, V,
        0LL, (long long)NK * V, (long long)O * NK,
        nullptr, 0LL, 0.0f);

    // K1: S[b][q][k] = scale * <Q,K>, mask==0 -> MASKV      -> fp16
    gemm_a32<1><<<dim3(NK / BN, NQ / BM, B), 256, SMEM_DYN>>>(
        queries, keys, S, NK, D,
        (long long)NQ * D, (long long)NK * D, (long long)NQ * NK,
        mask, (long long)NQ * NK, scale);

    // K2: softmax over last dim (fp16)
    softmax_rows_h<<<B * NQ, 256>>>(S);

    // K3: out[b][q][o] = sum_k P[b][q][k] * Vt[b][o][k] + bias[o]   (fp16 x fp16 -> fp32)
    gemm_h16<<<dim3(O / BN, NQ / BM, B), 256, SMEM_DYN>>>(
        S, Vt, out, O, NK,
        (long long)NQ * NK, (long long)O * NK, (long long)NQ * O,
        bias);
}

// round 7
// speedup vs baseline: 1.7645x; 1.0920x over previous
#include <cuda_runtime.h>
#include <cuda_fp16.h>
#include <stdint.h>

// ---------------- scratch (alloc-free: __device__ globals) ----------------
__device__ __half g_S [16u * 1024u * 2048u];   // logits / probs  [B,NQ,NK]  fp16
__device__ __half g_Vt[16u * 256u  * 2048u];   // V'^T = W @ V^T  [B,O,NK]   fp16

#define MASKV (-60000.0f)   // fp16-representable "minus infinity"

// ---------------- helpers ----------------
__device__ __forceinline__ uint32_t smem_u32(const void* p) {
    uint32_t a;
    asm("{ .reg .u64 t; cvta.to.shared.u64 t, %1; cvt.u32.u64 %0, t; }" : "=r"(a) : "l"(p));
    return a;
}
__device__ __forceinline__ uint32_t f16x2(float lo, float hi) {
    uint32_t u;
    asm("cvt.rn.f16x2.f32 %0, %1, %2;" : "=r"(u) : "f"(hi), "f"(lo));
    return u;
}
__device__ __forceinline__ void mma_f16(float c[4], const uint32_t a[4], const uint32_t b[2]) {
    asm volatile(
        "mma.sync.aligned.m16n8k16.row.col.f32.f16.f16.f32 "
        "{%0,%1,%2,%3}, {%4,%5,%6,%7}, {%8,%9}, {%0,%1,%2,%3};"
        : "+f"(c[0]), "+f"(c[1]), "+f"(c[2]), "+f"(c[3])
        : "r"(a[0]), "r"(a[1]), "r"(a[2]), "r"(a[3]), "r"(b[0]), "r"(b[1]));
}
__device__ __forceinline__ void ldsm4(uint32_t& r0, uint32_t& r1, uint32_t& r2, uint32_t& r3,
                                      uint32_t addr) {
    asm volatile("ldmatrix.sync.aligned.m8n8.x4.shared.b16 {%0,%1,%2,%3}, [%4];"
                 : "=r"(r0), "=r"(r1), "=r"(r2), "=r"(r3) : "r"(addr));
}
__device__ __forceinline__ void sts64(uint32_t a, uint32_t x, uint32_t y) {
    asm volatile("st.shared.v2.b32 [%0], {%1,%2};" :: "r"(a), "r"(x), "r"(y) : "memory");
}
__device__ __forceinline__ void sts128(uint32_t a, uint4 v) {
    asm volatile("st.shared.v4.b32 [%0], {%1,%2,%3,%4};"
                 :: "r"(a), "r"(v.x), "r"(v.y), "r"(v.z), "r"(v.w) : "memory");
}

// ---------------- tiling ----------------
// CTA tile 128x128x32, 4 warps as 2(M) x 2(N), warp tile 64x64. 128 threads.
// Two CTAs co-resident per SM -> sync walls of one CTA overlap the other's math.
// fp16 smem rows: 32 halfs = 64B data, stride 80B (conflict-free ldmatrix).
constexpr int BM = 128, BN = 128, BK = 32;
constexpr int SBH   = 80;                 // bytes per smem row
constexpr int A_B   = BM * SBH;           // 10240
constexpr int STG_B = (BM + BN) * SBH;    // 20480 per stage
constexpr int SMEM_DYN = 2 * STG_B;       // 40960

// ===================== GEMM: fp32 inputs -> fp16 output =====================
// C[z][m][n] = sum_k A[z][m][k] * B[z][n][k]
// EPI 0: plain (K0: Vt).  EPI 1: scale + mask -> MASKV (K1: logits)
template <int EPI>
__global__ __launch_bounds__(128, 2)
void gemm_a32(const float* __restrict__ Ag, const float* __restrict__ Bg,
              __half* __restrict__ Cg, int N, int K,
              long long sA, long long sB, long long sC,
              const int* __restrict__ maskg, long long sMask, float scale)
{
    extern __shared__ char smem[];

    const int tid  = threadIdx.x;
    const int lane = tid & 31;
    const int warp = tid >> 5;
    const int wm = (warp & 1) * 64;
    const int wn = (warp >> 1) * 64;
    const int z  = blockIdx.z;
    const int m0 = blockIdx.y * BM;
    const int n0 = blockIdx.x * BN;

    const float* A = Ag + (size_t)z * sA;
    const float* B = Bg + (size_t)z * sB;

    const uint32_t sbase = smem_u32(smem);
    const uint32_t aRowB = (uint32_t)(wm + (lane & 15)) * SBH + (uint32_t)(lane >> 4) * 16;
    const uint32_t bRowB = (uint32_t)(wn + (lane & 7) + ((lane >> 4) << 3)) * SBH
                         + (uint32_t)((lane >> 3) & 1) * 16;
    const int KT = K / BK;

    float4 ra[8], rb[8];
    auto load_regs = [&](int c) {
        const int koff = c * BK;
#pragma unroll
        for (int i = 0; i < 8; i++) {                   // A: 128 rows x 8 float4
            int f = tid + 128 * i, r = f >> 3, q = (f & 7) * 4;
            ra[i] = *(const float4*)(A + (size_t)(m0 + r) * K + koff + q);
        }
#pragma unroll
        for (int i = 0; i < 8; i++) {                   // B: 128 rows x 8 float4
            int f = tid + 128 * i, r = f >> 3, q = (f & 7) * 4;
            rb[i] = *(const float4*)(B + (size_t)(n0 + r) * K + koff + q);
        }
    };
    auto store_stage = [&](int s) {
        const uint32_t st = sbase + (uint32_t)s * STG_B;
#pragma unroll
        for (int i = 0; i < 8; i++) {
            int f = tid + 128 * i, r = f >> 3, q = (f & 7) * 4;
            sts64(st + (uint32_t)r * SBH + (uint32_t)q * 2,
                  f16x2(ra[i].x, ra[i].y), f16x2(ra[i].z, ra[i].w));
        }
#pragma unroll
        for (int i = 0; i < 8; i++) {
            int f = tid + 128 * i, r = f >> 3, q = (f & 7) * 4;
            sts64(st + (uint32_t)A_B + (uint32_t)r * SBH + (uint32_t)q * 2,
                  f16x2(rb[i].x, rb[i].y), f16x2(rb[i].z, rb[i].w));
        }
    };

    float acc[4][8][4];
#pragma unroll
    for (int i = 0; i < 4; i++)
#pragma unroll
        for (int j = 0; j < 8; j++)
#pragma unroll
            for (int r = 0; r < 4; r++) acc[i][j][r] = 0.0f;

    load_regs(0);
    store_stage(0);
    __syncthreads();
    if (KT > 1) load_regs(1);

    for (int kb = 0; kb < KT; ++kb) {
        const int cur = kb & 1;
        if (kb + 1 < KT) store_stage(cur ^ 1);
        if (kb + 2 < KT) load_regs(kb + 2);

        const uint32_t curBase = sbase + (uint32_t)cur * STG_B;
        const uint32_t aB = curBase + aRowB;
        const uint32_t bB = curBase + (uint32_t)A_B + bRowB;

#pragma unroll
        for (int ks = 0; ks < 2; ++ks) {                // 2 x K=16 per chunk
            const uint32_t kB = (uint32_t)ks * 32;
            uint32_t af[4][4], bf[8][2];
#pragma unroll
            for (int mi = 0; mi < 4; mi++)
                ldsm4(af[mi][0], af[mi][1], af[mi][2], af[mi][3],
                      aB + (uint32_t)mi * (16 * SBH) + kB);
#pragma unroll
            for (int pr = 0; pr < 4; pr++)
                ldsm4(bf[2 * pr][0], bf[2 * pr][1], bf[2 * pr + 1][0], bf[2 * pr + 1][1],
                      bB + (uint32_t)pr * (16 * SBH) + kB);
#pragma unroll
            for (int mi = 0; mi < 4; mi++)
#pragma unroll
                for (int ni = 0; ni < 8; ni++)
                    mma_f16(acc[mi][ni], af[mi], bf[ni]);
        }
        __syncthreads();
    }

    // ---------------- epilogue: fp16 out ----------------
    __half* C = Cg + (size_t)z * sC;
    const int* Mk = (EPI == 1) ? (maskg + (size_t)z * sMask) : (const int*)0;

#pragma unroll
    for (int mi = 0; mi < 4; mi++) {
#pragma unroll
        for (int ni = 0; ni < 8; ni++) {
            const int row0 = m0 + wm + mi * 16 + (lane >> 2);
            const int col  = n0 + wn + ni * 8 + (lane & 3) * 2;
#pragma unroll
            for (int h = 0; h < 2; ++h) {
                const int row = row0 + h * 8;
                float v0 = acc[mi][ni][2 * h];
                float v1 = acc[mi][ni][2 * h + 1];
                if (EPI == 1) {
                    v0 *= scale; v1 *= scale;
                    int2 mk = *(const int2*)(Mk + (size_t)row * N + col);
                    if (mk.x == 0) v0 = MASKV;
                    if (mk.y == 0) v1 = MASKV;
                }
                *(__half2*)(C + (size_t)row * N + col) = __floats2half2_rn(v0, v1);
            }
        }
    }
}

// ===================== GEMM: fp16 inputs -> fp32 output + bias (K3) ========
__global__ __launch_bounds__(128, 2)
void gemm_h16(const __half* __restrict__ Ag, const __half* __restrict__ Bg,
              float* __restrict__ Cg, int N, int K,
              long long sA, long long sB, long long sC,
              const float* __restrict__ bias)
{
    extern __shared__ char smem[];

    const int tid  = threadIdx.x;
    const int lane = tid & 31;
    const int warp = tid >> 5;
    const int wm = (warp & 1) * 64;
    const int wn = (warp >> 1) * 64;
    const int z  = blockIdx.z;
    const int m0 = blockIdx.y * BM;
    const int n0 = blockIdx.x * BN;

    const __half* A = Ag + (size_t)z * sA;
    const __half* B = Bg + (size_t)z * sB;

    const uint32_t sbase = smem_u32(smem);
    const uint32_t aRowB = (uint32_t)(wm + (lane & 15)) * SBH + (uint32_t)(lane >> 4) * 16;
    const uint32_t bRowB = (uint32_t)(wn + (lane & 7) + ((lane >> 4) << 3)) * SBH
                         + (uint32_t)((lane >> 3) & 1) * 16;
    const int KT = K / BK;

    uint4 ra[4], rb[4];
    auto load_regs = [&](int c) {
        const int koff = c * BK;
#pragma unroll
        for (int i = 0; i < 4; i++) {                   // A: 128 rows x 4 uint4
            int f = tid + 128 * i, r = f >> 2, sg = f & 3;
            ra[i] = *(const uint4*)(A + (size_t)(m0 + r) * K + koff + sg * 8);
        }
#pragma unroll
        for (int i = 0; i < 4; i++) {                   // B: 128 rows x 4 uint4
            int f = tid + 128 * i, r = f >> 2, sg = f & 3;
            rb[i] = *(const uint4*)(B + (size_t)(n0 + r) * K + koff + sg * 8);
        }
    };
    auto store_stage = [&](int s) {
        const uint32_t st = sbase + (uint32_t)s * STG_B;
#pragma unroll
        for (int i = 0; i < 4; i++) {
            int f = tid + 128 * i, r = f >> 2, sg = f & 3;
            sts128(st + (uint32_t)r * SBH + (uint32_t)sg * 16, ra[i]);
        }
#pragma unroll
        for (int i = 0; i < 4; i++) {
            int f = tid + 128 * i, r = f >> 2, sg = f & 3;
            sts128(st + (uint32_t)A_B + (uint32_t)r * SBH + (uint32_t)sg * 16, rb[i]);
        }
    };

    float acc[4][8][4];
#pragma unroll
    for (int i = 0; i < 4; i++)
#pragma unroll
        for (int j = 0; j < 8; j++)
#pragma unroll
            for (int r = 0; r < 4; r++) acc[i][j][r] = 0.0f;

    load_regs(0);
    store_stage(0);
    __syncthreads();
    if (KT > 1) load_regs(1);

    for (int kb = 0; kb < KT; ++kb) {
        const int cur = kb & 1;
        if (kb + 1 < KT) store_stage(cur ^ 1);
        if (kb + 2 < KT) load_regs(kb + 2);

        const uint32_t curBase = sbase + (uint32_t)cur * STG_B;
        const uint32_t aB = curBase + aRowB;
        const uint32_t bB = curBase + (uint32_t)A_B + bRowB;

#pragma unroll
        for (int ks = 0; ks < 2; ++ks) {
            const uint32_t kB = (uint32_t)ks * 32;
            uint32_t af[4][4], bf[8][2];
#pragma unroll
            for (int mi = 0; mi < 4; mi++)
                ldsm4(af[mi][0], af[mi][1], af[mi][2], af[mi][3],
                      aB + (uint32_t)mi * (16 * SBH) + kB);
#pragma unroll
            for (int pr = 0; pr < 4; pr++)
                ldsm4(bf[2 * pr][0], bf[2 * pr][1], bf[2 * pr + 1][0], bf[2 * pr + 1][1],
                      bB + (uint32_t)pr * (16 * SBH) + kB);
#pragma unroll
            for (int mi = 0; mi < 4; mi++)
#pragma unroll
                for (int ni = 0; ni < 8; ni++)
                    mma_f16(acc[mi][ni], af[mi], bf[ni]);
        }
        __syncthreads();
    }

    // ---------------- epilogue: fp32 out + bias ----------------
    float* C = Cg + (size_t)z * sC;
#pragma unroll
    for (int mi = 0; mi < 4; mi++) {
#pragma unroll
        for (int ni = 0; ni < 8; ni++) {
            const int row0 = m0 + wm + mi * 16 + (lane >> 2);
            const int col  = n0 + wn + ni * 8 + (lane & 3) * 2;
            const float b0 = bias[col], b1 = bias[col + 1];
#pragma unroll
            for (int h = 0; h < 2; ++h) {
                const int row = row0 + h * 8;
                float2 o;
                o.x = acc[mi][ni][2 * h]     + b0;
                o.y = acc[mi][ni][2 * h + 1] + b1;
                *(float2*)(C + (size_t)row * N + col) = o;
            }
        }
    }
}

// ---------------- row softmax over NK=2048, fp16 in/out ----------------
__global__ __launch_bounds__(256)
void softmax_rows_h(__half* __restrict__ S)
{
    __half* row = S + (size_t)blockIdx.x * 2048;
    const int tid = threadIdx.x;

    float4 raw = reinterpret_cast<float4*>(row)[tid];   // 8 halfs
    __half2* hp = (__half2*)&raw;
    float2 f[4];
#pragma unroll
    for (int i = 0; i < 4; i++) f[i] = __half22float2(hp[i]);

    float m = fmaxf(fmaxf(fmaxf(f[0].x, f[0].y), fmaxf(f[1].x, f[1].y)),
                    fmaxf(fmaxf(f[2].x, f[2].y), fmaxf(f[3].x, f[3].y)));
#pragma unroll
    for (int o = 16; o; o >>= 1) m = fmaxf(m, __shfl_xor_sync(0xffffffffu, m, o));

    __shared__ float red[8];
    if ((tid & 31) == 0) red[tid >> 5] = m;
    __syncthreads();
    m = red[0];
#pragma unroll
    for (int i = 1; i < 8; i++) m = fmaxf(m, red[i]);

    float s = 0.0f;
#pragma unroll
    for (int i = 0; i < 4; i++) {
        f[i].x = __expf(f[i].x - m);
        f[i].y = __expf(f[i].y - m);
        s += f[i].x + f[i].y;
    }
#pragma unroll
    for (int o = 16; o; o >>= 1) s += __shfl_xor_sync(0xffffffffu, s, o);

    __syncthreads();
    if ((tid & 31) == 0) red[tid >> 5] = s;
    __syncthreads();
    s = red[0];
#pragma unroll
    for (int i = 1; i < 8; i++) s += red[i];

    const float inv = 1.0f / s;
#pragma unroll
    for (int i = 0; i < 4; i++)
        hp[i] = __floats2half2_rn(f[i].x * inv, f[i].y * inv);
    reinterpret_cast<float4*>(row)[tid] = raw;
}

// ---------------- launch ----------------
extern "C" void kernel_launch(void* const* d_in, const int* in_sizes, int n_in,
                              void* d_out, int out_size)
{
    const float* keys    = (const float*)d_in[0];   // [16, 2048, 512]
    const float* queries = (const float*)d_in[1];   // [16, 1024, 512]
    const float* values  = (const float*)d_in[2];   // [16, 2048, 512]
    const int*   mask    = (const int*)  d_in[3];   // [16, 1024, 2048]
    const float* W       = (const float*)d_in[4];   // [256, 512]
    const float* bias    = (const float*)d_in[5];   // [256]
    float* out = (float*)d_out;                     // [16, 1024, 256]

    const int B = 16, NQ = 1024, NK = 2048, D = 512, V = 512, O = 256;
    const float scale = 1.0f / sqrtf(512.0f);       // KQ = 512

    __half* S = nullptr;  __half* Vt = nullptr;
    cudaGetSymbolAddress((void**)&S,  g_S);
    cudaGetSymbolAddress((void**)&Vt, g_Vt);

    cudaFuncSetAttribute(gemm_a32<0>, cudaFuncAttributeMaxDynamicSharedMemorySize, SMEM_DYN);
    cudaFuncSetAttribute(gemm_a32<1>, cudaFuncAttributeMaxDynamicSharedMemorySize, SMEM_DYN);
    cudaFuncSetAttribute(gemm_h16,    cudaFuncAttributeMaxDynamicSharedMemorySize, SMEM_DYN);

    // K0: Vt[b][o][n] = sum_v W[o][v] * values[b][n][v]     -> fp16
    gemm_a32<0><<<dim3(NK / BN, O / BM, B), 128, SMEM_DYN>>>(
        W, values, Vt, NK, V,
        0LL, (long long)NK * V, (long long)O * NK,
        nullptr, 0LL, 0.0f);

    // K1: S[b][q][k] = scale * <Q,K>, mask==0 -> MASKV      -> fp16
    gemm_a32<1><<<dim3(NK / BN, NQ / BM, B), 128, SMEM_DYN>>>(
        queries, keys, S, NK, D,
        (long long)NQ * D, (long long)NK * D, (long long)NQ * NK,
        mask, (long long)NQ * NK, scale);

    // K2: softmax over last dim (fp16)
    softmax_rows_h<<<B * NQ, 256>>>(S);

    // K3: out[b][q][o] = sum_k P[b][q][k] * Vt[b][o][k] + bias[o]   (fp16 x fp16 -> fp32)
    gemm_h16<<<dim3(O / BN, NQ / BM, B), 128, SMEM_DYN>>>(
        S, Vt, out, O, NK,
        (long long)NQ * NK, (long long)O * NK, (long long)NQ * O,
        bias);
}